// round 11
// baseline (speedup 1.0000x reference)
#include <cuda_runtime.h>
#include <cuda_bf16.h>
#include <math.h>
#include <stdint.h>

#define NPTS 4096
#define DIM  1024
#define NPOSD 7
#define NNEGD 4088
#define KSEL 17
#define ALPHA_C 30.0f
#define OFF_POS 4
#define OFF_NEG (4 + NPTS * NPOSD)

// GEMM: CTA tile 128x128, warp tile 64x32, int8 single-pass K=1024, BK=128B
#define NB 32
#define KITERS 8
#define STAGES 3
#define TILE_BYTES (128 * 128)
#define STAGE_BYTES (2 * TILE_BYTES)
#define EPI_PITCH 133
#define GEMM_SMEM (STAGES * STAGE_BYTES)  // 98304

__device__ signed char g_q[NPTS * DIM];
__device__ float g_scale[NPTS];
__device__ float g_sq[NPTS];
__device__ float g_loss[NPTS];
__device__ float g_psum[NPTS];
__device__ float g_nsum[NPTS];
__device__ int   g_ctr;

// ---------------------------------------------------------------------------
__device__ __forceinline__ uint32_t smem_u32(const void* p) {
    uint32_t a;
    asm("{ .reg .u64 t; cvta.to.shared.u64 t, %1; cvt.u32.u64 %0, t; }" : "=r"(a) : "l"(p));
    return a;
}
__device__ __forceinline__ void cp_async16(uint32_t dst, const void* src) {
    asm volatile("cp.async.cg.shared.global [%0], [%1], 16;" :: "r"(dst), "l"(src));
}
__device__ __forceinline__ void cp_commit() { asm volatile("cp.async.commit_group;"); }
template <int N>
__device__ __forceinline__ void cp_wait() {
    asm volatile("cp.async.wait_group %0;" :: "n"(N));
}
__device__ __forceinline__ void ldsm4(uint32_t* r, uint32_t addr) {
    asm volatile("ldmatrix.sync.aligned.m8n8.x4.shared.b16 {%0,%1,%2,%3}, [%4];"
                 : "=r"(r[0]), "=r"(r[1]), "=r"(r[2]), "=r"(r[3]) : "r"(addr));
}
__device__ __forceinline__ void imma16832(int* d, const uint32_t* a,
                                          uint32_t b0, uint32_t b1) {
    asm volatile("mma.sync.aligned.m16n8k32.row.col.s32.s8.s8.s32 "
                 "{%0,%1,%2,%3}, {%4,%5,%6,%7}, {%8,%9}, {%0,%1,%2,%3};"
                 : "+r"(d[0]), "+r"(d[1]), "+r"(d[2]), "+r"(d[3])
                 : "r"(a[0]), "r"(a[1]), "r"(a[2]), "r"(a[3]), "r"(b0), "r"(b1));
}

// ---------------------------------------------------------------------------
__device__ __forceinline__ float fast_exp(float a) {
    float y = a * 1.4426950408889634f;
    float n = rintf(y);
    float f = y - n;
    float p = 1.525273380405984e-5f;
    p = fmaf(p, f, 1.540353039338161e-4f);
    p = fmaf(p, f, 1.333355814642844e-3f);
    p = fmaf(p, f, 9.618129107628477e-3f);
    p = fmaf(p, f, 5.550410866482158e-2f);
    p = fmaf(p, f, 2.402265069591007e-1f);
    p = fmaf(p, f, 6.931471805599453e-1f);
    p = fmaf(p, f, 1.0f);
    int e = (int)n;
    return p * __int_as_float((e + 127) << 23);
}
__device__ __forceinline__ int out_index(int i, int j) {
    int lo = (i >> 3) << 3;
    unsigned rel = (unsigned)(j - lo);
    if (rel < 8u) {
        int p = j - lo - (j > i ? 1 : 0);
        return OFF_POS + i * NPOSD + p;
    }
    int p = (j < lo) ? j : (j - 8);
    return OFF_NEG + i * NNEGD + p;
}
__device__ __forceinline__ float block_sum256(float v, float* buf) {
    int t = threadIdx.x;
#pragma unroll
    for (int d = 16; d > 0; d >>= 1) v += __shfl_down_sync(0xFFFFFFFFu, v, d);
    if ((t & 31) == 0) buf[t >> 5] = v;
    __syncthreads();
    if (t < 32) {
        float x = (t < 8) ? buf[t] : 0.0f;
#pragma unroll
        for (int d = 4; d > 0; d >>= 1) x += __shfl_down_sync(0xFFFFFFFFu, x, d);
        if (t == 0) buf[0] = x;
    }
    __syncthreads();
    float r = buf[0];
    __syncthreads();
    return r;
}
__device__ __forceinline__ float block_min256(float v, float* buf) {
    int t = threadIdx.x;
#pragma unroll
    for (int d = 16; d > 0; d >>= 1) v = fminf(v, __shfl_down_sync(0xFFFFFFFFu, v, d));
    if ((t & 31) == 0) buf[t >> 5] = v;
    __syncthreads();
    if (t < 32) {
        float x = (t < 8) ? buf[t] : __int_as_float(0x7f800000);
#pragma unroll
        for (int d = 4; d > 0; d >>= 1) x = fminf(x, __shfl_down_sync(0xFFFFFFFFu, x, d));
        if (t == 0) buf[0] = x;
    }
    __syncthreads();
    float r = buf[0];
    __syncthreads();
    return r;
}

// ---------------------------------------------------------------------------
// Kernel 1: per-row max-abs + int8 quantize + exact squared norm + ctr reset
// ---------------------------------------------------------------------------
__global__ __launch_bounds__(128) void prep_kernel(const float* __restrict__ X) {
    int i = blockIdx.x, t = threadIdx.x;
    if (i == 0 && t == 0) g_ctr = 0;
    const float4* row = (const float4*)(X + (size_t)i * DIM);
    float4 x0 = row[t * 2], x1 = row[t * 2 + 1];
    float xs[8] = {x0.x, x0.y, x0.z, x0.w, x1.x, x1.y, x1.z, x1.w};

    float s = 0.0f, mx = 0.0f;
#pragma unroll
    for (int e = 0; e < 8; e++) {
        s = fmaf(xs[e], xs[e], s);
        mx = fmaxf(mx, fabsf(xs[e]));
    }
    __shared__ float sbuf[4], mbuf[4];
#pragma unroll
    for (int d = 16; d > 0; d >>= 1) {
        s += __shfl_down_sync(0xFFFFFFFFu, s, d);
        mx = fmaxf(mx, __shfl_down_sync(0xFFFFFFFFu, mx, d));
    }
    if ((t & 31) == 0) { sbuf[t >> 5] = s; mbuf[t >> 5] = mx; }
    __syncthreads();
    float maxv = fmaxf(fmaxf(mbuf[0], mbuf[1]), fmaxf(mbuf[2], mbuf[3]));
    if (t == 0) {
        g_sq[i] = sbuf[0] + sbuf[1] + sbuf[2] + sbuf[3];
        g_scale[i] = maxv * (1.0f / 127.0f);
    }
    float inv = 127.0f / maxv;
    uint32_t w0 = 0, w1 = 0;
#pragma unroll
    for (int e = 0; e < 4; e++) {
        int q = __float2int_rn(xs[e] * inv);
        w0 |= ((uint32_t)q & 255u) << (e * 8);
    }
#pragma unroll
    for (int e = 0; e < 4; e++) {
        int q = __float2int_rn(xs[e + 4] * inv);
        w1 |= ((uint32_t)q & 255u) << (e * 8);
    }
    *(uint2*)(g_q + (size_t)i * DIM + t * 8) = make_uint2(w0, w1);
}

// ---------------------------------------------------------------------------
// Kernel 2: int8 IMMA GEMM (m16n8k32), 128x128 triangular tiles, 2 CTAs/SM,
// 3-stage cp.async, fused dequant+dist epilogue, smem-staged coalesced writes.
// (unchanged from R10)
// ---------------------------------------------------------------------------
__global__ __launch_bounds__(256, 2) void gemm_dist_kernel(float* __restrict__ out) {
    extern __shared__ __align__(128) unsigned char smem_raw[];
    uint32_t sbase = smem_u32(smem_raw);

    int b = blockIdx.x;
    int bi = 0, rem = b;
    while (rem >= NB - bi) { rem -= NB - bi; bi++; }
    int bj = bi + rem;

    int tid = threadIdx.x;
    int wid = tid >> 5, lane = tid & 31;
    int wm = wid >> 2, wn = wid & 3;
    int mbase = wm * 64, nbase = wn * 32;

    int ldrow = tid >> 1;
    int ldq = (tid & 1) * 4;

    int acc[4][4][4];
#pragma unroll
    for (int mt = 0; mt < 4; mt++)
#pragma unroll
        for (int nt = 0; nt < 4; nt++)
#pragma unroll
            for (int e = 0; e < 4; e++) acc[mt][nt][e] = 0;

    auto issue_load = [&](int stage, int c) {
        int kk = c * 128;
        uint32_t sA = sbase + stage * STAGE_BYTES;
        uint32_t sB = sA + TILE_BYTES;
        const signed char* ga = g_q + (size_t)(bi * 128 + ldrow) * DIM + kk;
        const signed char* gb = g_q + (size_t)(bj * 128 + ldrow) * DIM + kk;
        uint32_t rowoff = (uint32_t)ldrow * 128;
        uint32_t r7 = (uint32_t)(ldrow & 7);
#pragma unroll
        for (int j = 0; j < 4; j++) {
            uint32_t ch = (uint32_t)(ldq + j);
            uint32_t sw = rowoff + ((ch ^ r7) << 4);
            cp_async16(sA + sw, ga + ch * 16);
            cp_async16(sB + sw, gb + ch * 16);
        }
    };

#pragma unroll
    for (int s = 0; s < STAGES - 1; s++) { issue_load(s, s); cp_commit(); }

    int lrow = lane & 15, lch = lane >> 4;

    int st = 0, ld_st = STAGES - 1;
    for (int c = 0; c < KITERS; c++) {
        cp_wait<STAGES - 2>();
        __syncthreads();
        uint32_t sA = sbase + st * STAGE_BYTES;
        uint32_t sB = sA + TILE_BYTES;
#pragma unroll
        for (int ks = 0; ks < 4; ks++) {
            uint32_t af[4][4], bf[2][4];
            uint32_t chsel = (uint32_t)(ks * 2 + lch);
#pragma unroll
            for (int mt = 0; mt < 4; mt++) {
                uint32_t r = (uint32_t)(mbase + mt * 16 + lrow);
                ldsm4(af[mt], sA + r * 128 + ((chsel ^ (r & 7)) << 4));
            }
#pragma unroll
            for (int nb2 = 0; nb2 < 2; nb2++) {
                uint32_t r = (uint32_t)(nbase + nb2 * 16 + lrow);
                ldsm4(bf[nb2], sB + r * 128 + ((chsel ^ (r & 7)) << 4));
            }
#pragma unroll
            for (int mt = 0; mt < 4; mt++)
#pragma unroll
                for (int nt = 0; nt < 4; nt++)
                    imma16832(acc[mt][nt], af[mt], bf[nt >> 1][nt & 1],
                              bf[nt >> 1][(nt & 1) + 2]);
        }
        if (c + STAGES - 1 < KITERS) issue_load(ld_st, c + STAGES - 1);
        cp_commit();
        st = (st == STAGES - 1) ? 0 : st + 1;
        ld_st = (ld_st == STAGES - 1) ? 0 : ld_st + 1;
    }

    __syncthreads();
    float* S = (float*)smem_raw;
    int r_in = lane >> 2, c_in = (lane & 3) * 2;
#pragma unroll
    for (int mt = 0; mt < 4; mt++) {
        int lr0 = mbase + mt * 16 + r_in;
        int gr0 = bi * 128 + lr0;
        float sq_r0 = __ldg(&g_sq[gr0]);
        float sq_r1 = __ldg(&g_sq[gr0 + 8]);
        float sc_r0 = __ldg(&g_scale[gr0]);
        float sc_r1 = __ldg(&g_scale[gr0 + 8]);
#pragma unroll
        for (int nt = 0; nt < 4; nt++) {
            int lc0 = nbase + nt * 8 + c_in;
            int gc0 = bj * 128 + lc0;
            float sq_c0 = __ldg(&g_sq[gc0]);
            float sq_c1 = __ldg(&g_sq[gc0 + 1]);
            float sc_c0 = __ldg(&g_scale[gc0]);
            float sc_c1 = __ldg(&g_scale[gc0 + 1]);
            float dot00 = (float)acc[mt][nt][0] * (sc_r0 * sc_c0);
            float dot01 = (float)acc[mt][nt][1] * (sc_r0 * sc_c1);
            float dot10 = (float)acc[mt][nt][2] * (sc_r1 * sc_c0);
            float dot11 = (float)acc[mt][nt][3] * (sc_r1 * sc_c1);
            S[lr0 * EPI_PITCH + lc0]           = sqrtf(fmaxf(sq_r0 + sq_c0 - 2.0f * dot00, 1e-12f));
            S[lr0 * EPI_PITCH + lc0 + 1]       = sqrtf(fmaxf(sq_r0 + sq_c1 - 2.0f * dot01, 1e-12f));
            S[(lr0 + 8) * EPI_PITCH + lc0]     = sqrtf(fmaxf(sq_r1 + sq_c0 - 2.0f * dot10, 1e-12f));
            S[(lr0 + 8) * EPI_PITCH + lc0 + 1] = sqrtf(fmaxf(sq_r1 + sq_c1 - 2.0f * dot11, 1e-12f));
        }
    }
    __syncthreads();

    for (int rr = wid; rr < 128; rr += 8) {
        int gi = bi * 128 + rr;
#pragma unroll
        for (int q = 0; q < 4; q++) {
            int cc = lane + q * 32;
            int gj = bj * 128 + cc;
            if (gi != gj) out[out_index(gi, gj)] = S[rr * EPI_PITCH + cc];
        }
    }
    if (bi != bj) {
        for (int rr = wid; rr < 128; rr += 8) {
            int gj = bj * 128 + rr;
#pragma unroll
            for (int q = 0; q < 4; q++) {
                int cc = lane + q * 32;
                out[out_index(gj, bi * 128 + cc)] = S[cc * EPI_PITCH + rr];
            }
        }
    }
}

// ---------------------------------------------------------------------------
// Kernel 3: per-row exact 17th-smallest via ATOMIC-FREE 4-bit radix with
// register-packed counters (16 bins x 16-bit in 4 uint64), + logits; last
// block does the final deterministic reduction.
// ---------------------------------------------------------------------------
__global__ __launch_bounds__(256) void row_select_kernel(float* __restrict__ out) {
    int i = blockIdx.x;
    int t = threadIdx.x;
    int w = t >> 5, lane = t & 31;
    const float* pos = out + OFF_POS + i * NPOSD;
    const float* neg = out + OFF_NEG + (size_t)i * NNEGD;

    float v[16];
    float psum = 0.0f, nsum = 0.0f;
    float minpos = __int_as_float(0x7f800000);
#pragma unroll
    for (int s = 0; s < 16; s++) {
        int idx = t + (s << 8);
        float val;
        if (idx < NPOSD) {
            val = pos[idx];
            psum += val;
            minpos = fminf(minpos, val);
        } else if (idx < NPOSD + NNEGD) {
            val = neg[idx - NPOSD];
            nsum += val;
        } else {
            val = __int_as_float(0x7f800000);   // +inf: digit7=7, never counted
        }
        v[s] = val;
    }

    // All real distances are positive floats < 2.0 => top nibble (bits>>28)==3.
    // (Values >= 2 would have nibble 4 and are correctly treated as > thr.)
    __shared__ unsigned long long cbuf[8][4];
    __shared__ unsigned long long ctot[4];
    __shared__ unsigned thrbits_s;

    unsigned prefix = 0x30000000u, pm = 0xF0000000u;
    int k = KSEL;
    float thr = 0.0f;
    bool done = false;

    for (int pass = 0; pass < 7 && !done; pass++) {
        int shift = 24 - pass * 4;
        unsigned long long c0 = 0, c1 = 0, c2 = 0, c3 = 0;
#pragma unroll
        for (int s = 0; s < 16; s++) {
            unsigned bb = __float_as_uint(v[s]);
            if ((bb & pm) == prefix) {
                unsigned d = (bb >> shift) & 15u;
                unsigned long long inc = 1ull << ((d & 3u) << 4);
                unsigned ws = d >> 2;
                c0 += (ws == 0u) ? inc : 0ull;
                c1 += (ws == 1u) ? inc : 0ull;
                c2 += (ws == 2u) ? inc : 0ull;
                c3 += (ws == 3u) ? inc : 0ull;
            }
        }
#pragma unroll
        for (int o = 16; o > 0; o >>= 1) {
            c0 += __shfl_down_sync(0xFFFFFFFFu, c0, o);
            c1 += __shfl_down_sync(0xFFFFFFFFu, c1, o);
            c2 += __shfl_down_sync(0xFFFFFFFFu, c2, o);
            c3 += __shfl_down_sync(0xFFFFFFFFu, c3, o);
        }
        if (lane == 0) {
            cbuf[w][0] = c0; cbuf[w][1] = c1; cbuf[w][2] = c2; cbuf[w][3] = c3;
        }
        __syncthreads();
        if (t < 4) {
            unsigned long long sm = 0;
#pragma unroll
            for (int w2 = 0; w2 < 8; w2++) sm += cbuf[w2][t];
            ctot[t] = sm;
        }
        __syncthreads();
        unsigned long long tot[4] = {ctot[0], ctot[1], ctot[2], ctot[3]};

        int cum = 0, selbin = 0, below = 0, selcnt = 0;
#pragma unroll
        for (int b2 = 0; b2 < 16; b2++) {
            int cnt = (int)((tot[b2 >> 2] >> ((b2 & 3) << 4)) & 0xFFFFull);
            bool hit = (cum < k) && (cum + cnt >= k);
            if (hit) { selbin = b2; below = cum; selcnt = cnt; }
            cum += cnt;
        }
        prefix |= ((unsigned)selbin) << shift;
        pm |= 0xFu << shift;
        k -= below;

        if (shift == 0) {
            thr = __uint_as_float(prefix);       // fully resolved
            done = true;
        } else if (selcnt == 1) {
            // unique survivor: scan for it (block-uniform branch)
#pragma unroll
            for (int s = 0; s < 16; s++) {
                unsigned bb = __float_as_uint(v[s]);
                if ((bb & pm) == prefix) thrbits_s = bb;
            }
            __syncthreads();
            thr = __uint_as_float(thrbits_s);
            done = true;
        }
        __syncthreads();
    }

    float pe = 0.0f, ne = 0.0f;
#pragma unroll
    for (int s = 0; s < 16; s++) {
        int idx = t + (s << 8);
        float d = v[s];
        if (idx < NPOSD + NNEGD && d < thr) {
            float e = fast_exp(ALPHA_C * (1.0f - d));
            if (idx < NPOSD) pe += e; else ne += e;
        }
    }

    __shared__ float rbuf[8];
    pe     = block_sum256(pe, rbuf);
    ne     = block_sum256(ne, rbuf);
    psum   = block_sum256(psum, rbuf);
    nsum   = block_sum256(nsum, rbuf);
    minpos = block_min256(minpos, rbuf);

    if (t == 0) {
        float pl = (minpos < thr) ? pe : fast_exp(ALPHA_C * (1.0f - minpos));
        g_loss[i] = logf(pl + ne) - logf(pl);
        g_psum[i] = psum;
        g_nsum[i] = nsum;
    }

    __threadfence();
    __shared__ int lastflag;
    if (t == 0) lastflag = (atomicAdd(&g_ctr, 1) == NPTS - 1) ? 1 : 0;
    __syncthreads();
    if (lastflag) {
        float ls = 0.0f, ac = 0.0f, ps = 0.0f, ns = 0.0f;
        for (int j = t; j < NPTS; j += 256) {
            float l = g_loss[j];
            ls += l;
            ac += (l < 0.6f) ? 1.0f : 0.0f;
            ps += g_psum[j];
            ns += g_nsum[j];
        }
        ls = block_sum256(ls, rbuf);
        ac = block_sum256(ac, rbuf);
        ps = block_sum256(ps, rbuf);
        ns = block_sum256(ns, rbuf);
        if (t == 0) {
            out[0] = ls / (float)NPTS;
            out[1] = ac / (float)NPTS;
            out[2] = ps / ((float)NPTS * (float)NPOSD);
            out[3] = ns / ((float)NPTS * (float)NNEGD);
        }
    }
}

// ---------------------------------------------------------------------------
extern "C" void kernel_launch(void* const* d_in, const int* in_sizes, int n_in,
                              void* d_out, int out_size) {
    const float* X = (const float*)d_in[0];
    float* out = (float*)d_out;
    (void)in_sizes; (void)n_in; (void)out_size;

    cudaFuncSetAttribute(gemm_dist_kernel, cudaFuncAttributeMaxDynamicSharedMemorySize,
                         GEMM_SMEM);
    prep_kernel<<<NPTS, 128>>>(X);
    gemm_dist_kernel<<<NB * (NB + 1) / 2, 256, GEMM_SMEM>>>(out);
    row_select_kernel<<<NPTS, 256>>>(out);
}

// round 14
// speedup vs baseline: 1.7358x; 1.7358x over previous
#include <cuda_runtime.h>
#include <cuda_bf16.h>
#include <math.h>
#include <stdint.h>

#define NPTS 4096
#define DIM  1024
#define NPOSD 7
#define NNEGD 4088
#define KSEL 17
#define ALPHA_C 30.0f
#define OFF_POS 4
#define OFF_NEG (4 + NPTS * NPOSD)

// GEMM: CTA tile 128x128, warp tile 64x32, int8 single-pass K=1024, BK=128B
#define NB 32
#define KITERS 8
#define STAGES 3
#define TILE_BYTES (128 * 128)
#define STAGE_BYTES (2 * TILE_BYTES)
#define EPI_PITCH 133
#define GEMM_SMEM (STAGES * STAGE_BYTES)  // 98304

#define FINF __int_as_float(0x7f800000)

__device__ signed char g_q[NPTS * DIM];
__device__ float g_scale[NPTS];
__device__ float g_sq[NPTS];
__device__ float g_loss[NPTS];
__device__ float g_psum[NPTS];
__device__ float g_nsum[NPTS];
__device__ int   g_ctr;

// ---------------------------------------------------------------------------
__device__ __forceinline__ uint32_t smem_u32(const void* p) {
    uint32_t a;
    asm("{ .reg .u64 t; cvta.to.shared.u64 t, %1; cvt.u32.u64 %0, t; }" : "=r"(a) : "l"(p));
    return a;
}
__device__ __forceinline__ void cp_async16(uint32_t dst, const void* src) {
    asm volatile("cp.async.cg.shared.global [%0], [%1], 16;" :: "r"(dst), "l"(src));
}
__device__ __forceinline__ void cp_commit() { asm volatile("cp.async.commit_group;"); }
template <int N>
__device__ __forceinline__ void cp_wait() {
    asm volatile("cp.async.wait_group %0;" :: "n"(N));
}
__device__ __forceinline__ void ldsm4(uint32_t* r, uint32_t addr) {
    asm volatile("ldmatrix.sync.aligned.m8n8.x4.shared.b16 {%0,%1,%2,%3}, [%4];"
                 : "=r"(r[0]), "=r"(r[1]), "=r"(r[2]), "=r"(r[3]) : "r"(addr));
}
__device__ __forceinline__ void imma16832(int* d, const uint32_t* a,
                                          uint32_t b0, uint32_t b1) {
    asm volatile("mma.sync.aligned.m16n8k32.row.col.s32.s8.s8.s32 "
                 "{%0,%1,%2,%3}, {%4,%5,%6,%7}, {%8,%9}, {%0,%1,%2,%3};"
                 : "+r"(d[0]), "+r"(d[1]), "+r"(d[2]), "+r"(d[3])
                 : "r"(a[0]), "r"(a[1]), "r"(a[2]), "r"(a[3]), "r"(b0), "r"(b1));
}

// ---------------------------------------------------------------------------
__device__ __forceinline__ float fast_exp(float a) {
    float y = a * 1.4426950408889634f;
    float n = rintf(y);
    float f = y - n;
    float p = 1.525273380405984e-5f;
    p = fmaf(p, f, 1.540353039338161e-4f);
    p = fmaf(p, f, 1.333355814642844e-3f);
    p = fmaf(p, f, 9.618129107628477e-3f);
    p = fmaf(p, f, 5.550410866482158e-2f);
    p = fmaf(p, f, 2.402265069591007e-1f);
    p = fmaf(p, f, 6.931471805599453e-1f);
    p = fmaf(p, f, 1.0f);
    int e = (int)n;
    return p * __int_as_float((e + 127) << 23);
}
__device__ __forceinline__ int out_index(int i, int j) {
    int lo = (i >> 3) << 3;
    unsigned rel = (unsigned)(j - lo);
    if (rel < 8u) {
        int p = j - lo - (j > i ? 1 : 0);
        return OFF_POS + i * NPOSD + p;
    }
    int p = (j < lo) ? j : (j - 8);
    return OFF_NEG + i * NNEGD + p;
}
__device__ __forceinline__ float block_sum256(float v, float* buf) {
    int t = threadIdx.x;
#pragma unroll
    for (int d = 16; d > 0; d >>= 1) v += __shfl_down_sync(0xFFFFFFFFu, v, d);
    if ((t & 31) == 0) buf[t >> 5] = v;
    __syncthreads();
    if (t < 32) {
        float x = (t < 8) ? buf[t] : 0.0f;
#pragma unroll
        for (int d = 4; d > 0; d >>= 1) x += __shfl_down_sync(0xFFFFFFFFu, x, d);
        if (t == 0) buf[0] = x;
    }
    __syncthreads();
    float r = buf[0];
    __syncthreads();
    return r;
}
__device__ __forceinline__ float block_min256(float v, float* buf) {
    int t = threadIdx.x;
#pragma unroll
    for (int d = 16; d > 0; d >>= 1) v = fminf(v, __shfl_down_sync(0xFFFFFFFFu, v, d));
    if ((t & 31) == 0) buf[t >> 5] = v;
    __syncthreads();
    if (t < 32) {
        float x = (t < 8) ? buf[t] : FINF;
#pragma unroll
        for (int d = 4; d > 0; d >>= 1) x = fminf(x, __shfl_down_sync(0xFFFFFFFFu, x, d));
        if (t == 0) buf[0] = x;
    }
    __syncthreads();
    float r = buf[0];
    __syncthreads();
    return r;
}

// ---------------------------------------------------------------------------
// Kernel 1: per-row max-abs + int8 quantize + exact squared norm + ctr reset
// ---------------------------------------------------------------------------
__global__ __launch_bounds__(128) void prep_kernel(const float* __restrict__ X) {
    int i = blockIdx.x, t = threadIdx.x;
    if (i == 0 && t == 0) g_ctr = 0;
    const float4* row = (const float4*)(X + (size_t)i * DIM);
    float4 x0 = row[t * 2], x1 = row[t * 2 + 1];
    float xs[8] = {x0.x, x0.y, x0.z, x0.w, x1.x, x1.y, x1.z, x1.w};

    float s = 0.0f, mx = 0.0f;
#pragma unroll
    for (int e = 0; e < 8; e++) {
        s = fmaf(xs[e], xs[e], s);
        mx = fmaxf(mx, fabsf(xs[e]));
    }
    __shared__ float sbuf[4], mbuf[4];
#pragma unroll
    for (int d = 16; d > 0; d >>= 1) {
        s += __shfl_down_sync(0xFFFFFFFFu, s, d);
        mx = fmaxf(mx, __shfl_down_sync(0xFFFFFFFFu, mx, d));
    }
    if ((t & 31) == 0) { sbuf[t >> 5] = s; mbuf[t >> 5] = mx; }
    __syncthreads();
    float maxv = fmaxf(fmaxf(mbuf[0], mbuf[1]), fmaxf(mbuf[2], mbuf[3]));
    if (t == 0) {
        g_sq[i] = sbuf[0] + sbuf[1] + sbuf[2] + sbuf[3];
        g_scale[i] = maxv * (1.0f / 127.0f);
    }
    float inv = 127.0f / maxv;
    uint32_t w0 = 0, w1 = 0;
#pragma unroll
    for (int e = 0; e < 4; e++) {
        int q = __float2int_rn(xs[e] * inv);
        w0 |= ((uint32_t)q & 255u) << (e * 8);
    }
#pragma unroll
    for (int e = 0; e < 4; e++) {
        int q = __float2int_rn(xs[e + 4] * inv);
        w1 |= ((uint32_t)q & 255u) << (e * 8);
    }
    *(uint2*)(g_q + (size_t)i * DIM + t * 8) = make_uint2(w0, w1);
}

// ---------------------------------------------------------------------------
// Kernel 2: int8 IMMA GEMM (m16n8k32), 128x128 triangular tiles, 2 CTAs/SM,
// 3-stage cp.async, fused dequant+dist epilogue, smem-staged coalesced writes.
// (unchanged from R10 best)
// ---------------------------------------------------------------------------
__global__ __launch_bounds__(256, 2) void gemm_dist_kernel(float* __restrict__ out) {
    extern __shared__ __align__(128) unsigned char smem_raw[];
    uint32_t sbase = smem_u32(smem_raw);

    int b = blockIdx.x;
    int bi = 0, rem = b;
    while (rem >= NB - bi) { rem -= NB - bi; bi++; }
    int bj = bi + rem;

    int tid = threadIdx.x;
    int wid = tid >> 5, lane = tid & 31;
    int wm = wid >> 2, wn = wid & 3;
    int mbase = wm * 64, nbase = wn * 32;

    int ldrow = tid >> 1;
    int ldq = (tid & 1) * 4;

    int acc[4][4][4];
#pragma unroll
    for (int mt = 0; mt < 4; mt++)
#pragma unroll
        for (int nt = 0; nt < 4; nt++)
#pragma unroll
            for (int e = 0; e < 4; e++) acc[mt][nt][e] = 0;

    auto issue_load = [&](int stage, int c) {
        int kk = c * 128;
        uint32_t sA = sbase + stage * STAGE_BYTES;
        uint32_t sB = sA + TILE_BYTES;
        const signed char* ga = g_q + (size_t)(bi * 128 + ldrow) * DIM + kk;
        const signed char* gb = g_q + (size_t)(bj * 128 + ldrow) * DIM + kk;
        uint32_t rowoff = (uint32_t)ldrow * 128;
        uint32_t r7 = (uint32_t)(ldrow & 7);
#pragma unroll
        for (int j = 0; j < 4; j++) {
            uint32_t ch = (uint32_t)(ldq + j);
            uint32_t sw = rowoff + ((ch ^ r7) << 4);
            cp_async16(sA + sw, ga + ch * 16);
            cp_async16(sB + sw, gb + ch * 16);
        }
    };

#pragma unroll
    for (int s = 0; s < STAGES - 1; s++) { issue_load(s, s); cp_commit(); }

    int lrow = lane & 15, lch = lane >> 4;

    int st = 0, ld_st = STAGES - 1;
    for (int c = 0; c < KITERS; c++) {
        cp_wait<STAGES - 2>();
        __syncthreads();
        uint32_t sA = sbase + st * STAGE_BYTES;
        uint32_t sB = sA + TILE_BYTES;
#pragma unroll
        for (int ks = 0; ks < 4; ks++) {
            uint32_t af[4][4], bf[2][4];
            uint32_t chsel = (uint32_t)(ks * 2 + lch);
#pragma unroll
            for (int mt = 0; mt < 4; mt++) {
                uint32_t r = (uint32_t)(mbase + mt * 16 + lrow);
                ldsm4(af[mt], sA + r * 128 + ((chsel ^ (r & 7)) << 4));
            }
#pragma unroll
            for (int nb2 = 0; nb2 < 2; nb2++) {
                uint32_t r = (uint32_t)(nbase + nb2 * 16 + lrow);
                ldsm4(bf[nb2], sB + r * 128 + ((chsel ^ (r & 7)) << 4));
            }
#pragma unroll
            for (int mt = 0; mt < 4; mt++)
#pragma unroll
                for (int nt = 0; nt < 4; nt++)
                    imma16832(acc[mt][nt], af[mt], bf[nt >> 1][nt & 1],
                              bf[nt >> 1][(nt & 1) + 2]);
        }
        if (c + STAGES - 1 < KITERS) issue_load(ld_st, c + STAGES - 1);
        cp_commit();
        st = (st == STAGES - 1) ? 0 : st + 1;
        ld_st = (ld_st == STAGES - 1) ? 0 : ld_st + 1;
    }

    __syncthreads();
    float* S = (float*)smem_raw;
    int r_in = lane >> 2, c_in = (lane & 3) * 2;
#pragma unroll
    for (int mt = 0; mt < 4; mt++) {
        int lr0 = mbase + mt * 16 + r_in;
        int gr0 = bi * 128 + lr0;
        float sq_r0 = __ldg(&g_sq[gr0]);
        float sq_r1 = __ldg(&g_sq[gr0 + 8]);
        float sc_r0 = __ldg(&g_scale[gr0]);
        float sc_r1 = __ldg(&g_scale[gr0 + 8]);
#pragma unroll
        for (int nt = 0; nt < 4; nt++) {
            int lc0 = nbase + nt * 8 + c_in;
            int gc0 = bj * 128 + lc0;
            float sq_c0 = __ldg(&g_sq[gc0]);
            float sq_c1 = __ldg(&g_sq[gc0 + 1]);
            float sc_c0 = __ldg(&g_scale[gc0]);
            float sc_c1 = __ldg(&g_scale[gc0 + 1]);
            float dot00 = (float)acc[mt][nt][0] * (sc_r0 * sc_c0);
            float dot01 = (float)acc[mt][nt][1] * (sc_r0 * sc_c1);
            float dot10 = (float)acc[mt][nt][2] * (sc_r1 * sc_c0);
            float dot11 = (float)acc[mt][nt][3] * (sc_r1 * sc_c1);
            S[lr0 * EPI_PITCH + lc0]           = sqrtf(fmaxf(sq_r0 + sq_c0 - 2.0f * dot00, 1e-12f));
            S[lr0 * EPI_PITCH + lc0 + 1]       = sqrtf(fmaxf(sq_r0 + sq_c1 - 2.0f * dot01, 1e-12f));
            S[(lr0 + 8) * EPI_PITCH + lc0]     = sqrtf(fmaxf(sq_r1 + sq_c0 - 2.0f * dot10, 1e-12f));
            S[(lr0 + 8) * EPI_PITCH + lc0 + 1] = sqrtf(fmaxf(sq_r1 + sq_c1 - 2.0f * dot11, 1e-12f));
        }
    }
    __syncthreads();

    for (int rr = wid; rr < 128; rr += 8) {
        int gi = bi * 128 + rr;
#pragma unroll
        for (int q = 0; q < 4; q++) {
            int cc = lane + q * 32;
            int gj = bj * 128 + cc;
            if (gi != gj) out[out_index(gi, gj)] = S[rr * EPI_PITCH + cc];
        }
    }
    if (bi != bj) {
        for (int rr = wid; rr < 128; rr += 8) {
            int gj = bj * 128 + rr;
#pragma unroll
            for (int q = 0; q < 4; q++) {
                int cc = lane + q * 32;
                out[out_index(gj, bi * 128 + cc)] = S[cc * EPI_PITCH + rr];
            }
        }
    }
}

// ---------------------------------------------------------------------------
// Kernel 3: per-row exact 17th-smallest (256-bin radix, proven R9/R10 path)
// with VECTORIZED float4 loads; invalid lanes = +inf (no validity branches).
// Last block does the final deterministic reduction.
// ---------------------------------------------------------------------------
__global__ __launch_bounds__(256) void row_select_kernel(float* __restrict__ out) {
    int i = blockIdx.x;
    int t = threadIdx.x;
    const float* pos = out + OFF_POS + i * NPOSD;
    const float4* nptr = (const float4*)(out + OFF_NEG + (size_t)i * NNEGD);  // 1022 vecs

    float v[17];
    float psum = 0.0f, nsum = 0.0f;
#pragma unroll
    for (int s = 0; s < 4; s++) {
        int q = t + (s << 8);
        if (q < 1022) {
            float4 x = nptr[q];
            v[s * 4 + 0] = x.x; v[s * 4 + 1] = x.y;
            v[s * 4 + 2] = x.z; v[s * 4 + 3] = x.w;
            nsum += (x.x + x.y) + (x.z + x.w);
        } else {
            v[s * 4 + 0] = FINF; v[s * 4 + 1] = FINF;
            v[s * 4 + 2] = FINF; v[s * 4 + 3] = FINF;
        }
    }
    v[16] = (t < NPOSD) ? pos[t] : FINF;
    if (t < NPOSD) psum = v[16];
    float minpos = v[16];                       // +inf for t>=7; min-reduced below

    // exact radix select (positive floats; +inf padding sorts last)
    __shared__ int hist[256];
    __shared__ int wsum[8];
    __shared__ int sel[2];
    unsigned prefix = 0u;
    int k = KSEL;
#pragma unroll
    for (int pass = 0; pass < 4; pass++) {
        int shift = 24 - pass * 8;
        hist[t] = 0;
        __syncthreads();
        unsigned pm = (pass == 0) ? 0u : (0xFFFFFFFFu << (shift + 8));
#pragma unroll
        for (int s = 0; s < 17; s++) {
            unsigned bb = __float_as_uint(v[s]);
            if ((bb & pm) == prefix) atomicAdd(&hist[(bb >> shift) & 255u], 1);
        }
        __syncthreads();
        int cnt = hist[t];
        int x = cnt;
#pragma unroll
        for (int d2 = 1; d2 < 32; d2 <<= 1) {
            int y = __shfl_up_sync(0xFFFFFFFFu, x, d2);
            if ((t & 31) >= d2) x += y;
        }
        if ((t & 31) == 31) wsum[t >> 5] = x;
        __syncthreads();
        if (t < 8) {
            int y = wsum[t];
#pragma unroll
            for (int d2 = 1; d2 < 8; d2 <<= 1) {
                int z = __shfl_up_sync(0xFFu, y, d2);
                if (t >= d2) y += z;
            }
            wsum[t] = y;
        }
        __syncthreads();
        int incl = x + ((t >= 32) ? wsum[(t >> 5) - 1] : 0);
        int excl = incl - cnt;
        if (incl >= k && excl < k) { sel[0] = t; sel[1] = excl; }
        __syncthreads();
        prefix |= ((unsigned)sel[0]) << shift;
        k -= sel[1];
        __syncthreads();
    }
    float thr = __uint_as_float(prefix);        // exact 17th smallest

    float pe = 0.0f, ne = 0.0f;
#pragma unroll
    for (int s = 0; s < 16; s++) {
        float d = v[s];
        if (d < thr) ne += fast_exp(ALPHA_C * (1.0f - d));   // +inf lanes excluded
    }
    if (v[16] < thr) pe = fast_exp(ALPHA_C * (1.0f - v[16]));

    __shared__ float rbuf[8];
    pe     = block_sum256(pe, rbuf);
    ne     = block_sum256(ne, rbuf);
    psum   = block_sum256(psum, rbuf);
    nsum   = block_sum256(nsum, rbuf);
    minpos = block_min256(minpos, rbuf);

    if (t == 0) {
        float pl = (minpos < thr) ? pe : fast_exp(ALPHA_C * (1.0f - minpos));
        g_loss[i] = logf(pl + ne) - logf(pl);
        g_psum[i] = psum;
        g_nsum[i] = nsum;
    }

    __threadfence();
    __shared__ int lastflag;
    if (t == 0) lastflag = (atomicAdd(&g_ctr, 1) == NPTS - 1) ? 1 : 0;
    __syncthreads();
    if (lastflag) {
        float ls = 0.0f, ac = 0.0f, ps = 0.0f, ns = 0.0f;
        for (int j = t; j < NPTS; j += 256) {
            float l = g_loss[j];
            ls += l;
            ac += (l < 0.6f) ? 1.0f : 0.0f;
            ps += g_psum[j];
            ns += g_nsum[j];
        }
        ls = block_sum256(ls, rbuf);
        ac = block_sum256(ac, rbuf);
        ps = block_sum256(ps, rbuf);
        ns = block_sum256(ns, rbuf);
        if (t == 0) {
            out[0] = ls / (float)NPTS;
            out[1] = ac / (float)NPTS;
            out[2] = ps / ((float)NPTS * (float)NPOSD);
            out[3] = ns / ((float)NPTS * (float)NNEGD);
        }
    }
}

// ---------------------------------------------------------------------------
extern "C" void kernel_launch(void* const* d_in, const int* in_sizes, int n_in,
                              void* d_out, int out_size) {
    const float* X = (const float*)d_in[0];
    float* out = (float*)d_out;
    (void)in_sizes; (void)n_in; (void)out_size;

    cudaFuncSetAttribute(gemm_dist_kernel, cudaFuncAttributeMaxDynamicSharedMemorySize,
                         GEMM_SMEM);
    prep_kernel<<<NPTS, 128>>>(X);
    gemm_dist_kernel<<<NB * (NB + 1) / 2, 256, GEMM_SMEM>>>(out);
    row_select_kernel<<<NPTS, 256>>>(out);
}